// round 15
// baseline (speedup 1.0000x reference)
#include <cuda_runtime.h>
#include <cstdint>

// ItemEncoder R14: HYBRID transport = R12 bulk pipeline (5/8 of groups)
//                  + 4 independent R1-style direct-LDG gather warps (3/8).
//   out[t,:] = M[ids[t],:] @ W^T + b ; 12800 tokens, D=2000, O=8.
//
// Rationale: R12 data shows the bulk path caps at ~15 B/cyc/SM (consumers
// idle on `full`); the LSU/LDG path has an independent outstanding-request
// window (~17 B/cyc/SM in R1). Use both at once.
//
//  - 1 CTA / SM, 416 threads = 13 warps:
//      warps 0-7 : bulk consumers (R12 verbatim: W in regs, XOR-rotated
//                  selection-free butterfly, 4-token stages)
//      warp  8   : producer (lane 0; one-time W->smem copy, then ring)
//      warps 9-12: LDG gather warps, each independently processing whole
//                  4-token groups R1-style (v via LDG.128, W via smem LDS,
//                  select-butterfly, direct store). No ring/bar coupling.
//  - Ring: NBUF=4 x 32256 B (128 KB in flight). W staged once to smem
//    (64000 B) for the LDG warps.

static constexpr int NTOK  = 12800;
static constexpr int D     = 2000;
static constexpr int ROWB  = D * 4;          // 8000 B
static constexpr int QPR   = D / 4;          // 500
static constexpr int STOK  = 4;
static constexpr int NSTG  = NTOK / STOK;    // 3200
static constexpr int NTHR  = 416;
static constexpr int NCONS = 256;            // bulk-consumer barrier width
static constexpr int NBUF  = 4;
static constexpr int STAGEB  = STOK * ROWB;  // 32000
static constexpr int BSTRIDE = 32256;        // +256 B zeroed pad (quads 500..511)
static constexpr int SM_W    = 0;                        // 64000 B (W rows)
static constexpr int SM_RING = 64000;
static constexpr int SM_RED  = SM_RING + NBUF * BSTRIDE; // 193024; red 2x1024 B
static constexpr int SM_MBAR = SM_RED + 2048;            // 195072
static constexpr int SM_TOT  = SM_MBAR + NBUF * 16 + 16; // + W mbar

__device__ __forceinline__ void ffma2(unsigned long long &acc,
                                      unsigned long long a,
                                      unsigned long long b) {
    asm("fma.rn.f32x2 %0, %1, %2, %0;" : "+l"(acc) : "l"(a), "l"(b));
}
__device__ __forceinline__ void mbar_init(uint32_t a, uint32_t cnt) {
    asm volatile("mbarrier.init.shared.b64 [%0], %1;" :: "r"(a), "r"(cnt) : "memory");
}
__device__ __forceinline__ void mbar_expect_tx(uint32_t a, uint32_t bytes) {
    asm volatile("mbarrier.arrive.expect_tx.shared.b64 _, [%0], %1;"
                 :: "r"(a), "r"(bytes) : "memory");
}
__device__ __forceinline__ void mbar_arrive(uint32_t a) {
    asm volatile("mbarrier.arrive.shared.b64 _, [%0];" :: "r"(a) : "memory");
}
__device__ __forceinline__ void mbar_wait(uint32_t a, uint32_t parity) {
    asm volatile(
        "{\n\t.reg .pred P;\n\t"
        "WL_%=:\n\t"
        "mbarrier.try_wait.parity.acquire.cta.shared::cta.b64 P, [%0], %1, 0x989680;\n\t"
        "@P bra WD_%=;\n\t"
        "bra WL_%=;\n\t"
        "WD_%=:\n\t}"
        :: "r"(a), "r"(parity) : "memory");
}
__device__ __forceinline__ void bulk_cp(uint32_t smem_dst, const void* gmem_src,
                                        uint32_t bytes, uint32_t mbar) {
    asm volatile(
        "cp.async.bulk.shared::cta.global.mbarrier::complete_tx::bytes "
        "[%0], [%1], %2, [%3];"
        :: "r"(smem_dst), "l"(gmem_src), "r"(bytes), "r"(mbar) : "memory");
}
__device__ __forceinline__ void bar_cons() {   // bulk consumers only (256 thr)
    asm volatile("bar.sync 1, %0;" :: "n"(NCONS) : "memory");
}

__global__ void __launch_bounds__(NTHR, 1)
gather_proj_r14(const int*   __restrict__ ids,
                const float* __restrict__ M,
                const float* __restrict__ W,
                const float* __restrict__ bias,
                float*       __restrict__ out)
{
    extern __shared__ char smem[];
    const uint32_t smem_u32 = (uint32_t)__cvta_generic_to_shared(smem);
    const int tid  = threadIdx.x;
    const int lane = tid & 31;
    const int wid  = tid >> 5;

    const int gridn  = gridDim.x;
    const int s0     = blockIdx.x;
    const int nLocal = (NSTG - s0 + gridn - 1) / gridn;   // >= 21
    const int L      = (nLocal * 3) / 8;                  // LDG-warp share
    const int B      = nLocal - L;                        // bulk share

    auto fullb  = [&](int s) -> uint32_t { return smem_u32 + SM_MBAR + s * 16; };
    auto emptyb = [&](int s) -> uint32_t { return smem_u32 + SM_MBAR + s * 16 + 8; };
    const uint32_t wmbar = smem_u32 + SM_MBAR + NBUF * 16;

    // ---- init: mbarriers + zero ring pads ----
    if (tid == 0) {
#pragma unroll
        for (int s = 0; s < NBUF; ++s) {
            mbar_init(fullb(s), 1);
            mbar_init(emptyb(s), 1);
        }
        mbar_init(wmbar, 1);
    }
    if (tid < NBUF * 16) {             // 4 x 256 B ring pads (quads 500..511)
        int b = tid >> 4, qq = tid & 15;
        *(float4*)(smem + SM_RING + b * BSTRIDE + STAGEB + qq * 16) =
            make_float4(0.f, 0.f, 0.f, 0.f);
    }
    const float bval = __ldg(bias + (lane & 7));
    __syncthreads();                   // mbarriers + pads visible to all

    if (wid == 8) {
        // ================= producer (lane 0) =================
        if (lane == 0) {
            const char* Mb = (const char*)M;
            // one-time: W (contiguous 8x2000 f32 = 64000 B) -> smem
            mbar_expect_tx(wmbar, 8 * ROWB);
            bulk_cp(smem_u32 + SM_W, W, 8 * ROWB, wmbar);

            int phase = 1;             // fresh empty barriers: first waits pass
            int4 nid = __ldg((const int4*)ids + s0);   // stage 0 ids
            for (int k = 0; k < B; ++k) {
                const int slot = k % NBUF;
                mbar_wait(emptyb(slot), phase);
                const uint32_t dst = smem_u32 + SM_RING + slot * BSTRIDE;
                mbar_expect_tx(fullb(slot), STAGEB);
                bulk_cp(dst,            Mb + (size_t)nid.x * ROWB, ROWB, fullb(slot));
                bulk_cp(dst + ROWB,     Mb + (size_t)nid.y * ROWB, ROWB, fullb(slot));
                bulk_cp(dst + 2 * ROWB, Mb + (size_t)nid.z * ROWB, ROWB, fullb(slot));
                bulk_cp(dst + 3 * ROWB, Mb + (size_t)nid.w * ROWB, ROWB, fullb(slot));
                if (k + 1 < B)         // ids pipelined one stage ahead
                    nid = __ldg((const int4*)ids + (s0 + (k + 1) * gridn));
                if (slot == NBUF - 1) phase ^= 1;
            }
        }
        return;
    }

    if (wid >= 9) {
        // ============ LDG gather warps (9-12): groups B..nLocal-1 ============
        mbar_wait(wmbar, 0);           // W staged in smem
        const ulonglong2* r4 = nullptr; (void)r4;

        for (int j = B + (wid - 9); j < nLocal; j += 4) {
            const int grp = s0 + j * gridn;
            const int4 ii = __ldg((const int4*)ids + grp);
            const ulonglong2* r0 = (const ulonglong2*)M + (size_t)ii.x * QPR;
            const ulonglong2* r1 = (const ulonglong2*)M + (size_t)ii.y * QPR;
            const ulonglong2* r2 = (const ulonglong2*)M + (size_t)ii.z * QPR;
            const ulonglong2* r3 = (const ulonglong2*)M + (size_t)ii.w * QPR;

            unsigned long long acc[4][8];
#pragma unroll
            for (int t = 0; t < 4; ++t)
#pragma unroll
                for (int o = 0; o < 8; ++o) acc[t][o] = 0ull;

            auto accum = [&](int q) {
                ulonglong2 v[4];
                v[0] = __ldg(r0 + q);
                v[1] = __ldg(r1 + q);
                v[2] = __ldg(r2 + q);
                v[3] = __ldg(r3 + q);
#pragma unroll
                for (int o = 0; o < 8; ++o) {
                    const ulonglong2 wv = *(const ulonglong2*)
                        (smem + SM_W + o * ROWB + q * 16);
#pragma unroll
                    for (int t = 0; t < 4; ++t) {
                        ffma2(acc[t][o], v[t].x, wv.x);
                        ffma2(acc[t][o], v[t].y, wv.y);
                    }
                }
            };

#pragma unroll 3
            for (int it = 0; it < 15; ++it)
                accum(it * 32 + lane);
            if (lane < 20)
                accum(480 + lane);

            // collapse + select-butterfly (R1-verified)
            float cur[32];
#pragma unroll
            for (int t = 0; t < 4; ++t)
#pragma unroll
                for (int o = 0; o < 8; ++o) {
                    const unsigned long long a = acc[t][o];
                    cur[t * 8 + o] = __uint_as_float((unsigned)a) +
                                     __uint_as_float((unsigned)(a >> 32));
                }
#pragma unroll
            for (int off = 16; off >= 1; off >>= 1) {
                const bool up = (lane & off) != 0;
#pragma unroll
                for (int j2 = 0; j2 < off; ++j2) {
                    float keep = up ? cur[j2 + off] : cur[j2];
                    float give = up ? cur[j2] : cur[j2 + off];
                    keep += __shfl_xor_sync(0xffffffffu, give, off);
                    cur[j2] = keep;
                }
            }
            out[(size_t)grp * 32 + lane] = cur[0] + bval;
        }
        return;
    }

    // ================= bulk consumers (warps 0-7), R12 verbatim ==============
    const int lt = lane >> 3;   // token rotation (2 bits)
    const int lo = lane & 7;    // output rotation (3 bits)

    // W into registers, XOR-rotated by lo (one-time, zeroed OOB)
    ulonglong2 w[2][8];
#pragma unroll
    for (int it = 0; it < 2; ++it) {
        const int q = wid * 64 + it * 32 + lane;
#pragma unroll
        for (int o = 0; o < 8; ++o) {
            if (q < QPR) w[it][o] = __ldg((const ulonglong2*)W + (o ^ lo) * QPR + q);
            else         w[it][o] = make_ulonglong2(0ull, 0ull);
        }
    }

    float* red = (float*)(smem + SM_RED);
    int slot = 0, phase = 0;

    for (int k = 0; k < B; ++k) {
        mbar_wait(fullb(slot), phase);
        const char* buf = smem + SM_RING + slot * BSTRIDE;

        unsigned long long acc[4][8];
#pragma unroll
        for (int t = 0; t < 4; ++t)
#pragma unroll
            for (int o = 0; o < 8; ++o) acc[t][o] = 0ull;

#pragma unroll
        for (int it = 0; it < 2; ++it) {
            const int q = wid * 64 + it * 32 + lane;   // 500..511 hit pad, w=0
            ulonglong2 v[4];
#pragma unroll
            for (int t = 0; t < 4; ++t)
                v[t] = *(const ulonglong2*)(buf + (t ^ lt) * ROWB + q * 16);
#pragma unroll
            for (int t = 0; t < 4; ++t)
#pragma unroll
                for (int o = 0; o < 8; ++o) {
                    ffma2(acc[t][o], v[t].x, w[it][o].x);
                    ffma2(acc[t][o], v[t].y, w[it][o].y);
                }
        }
        // acc slot j = t*8+o holds partial of value j^lane

        float cur[32];
#pragma unroll
        for (int t = 0; t < 4; ++t)
#pragma unroll
            for (int o = 0; o < 8; ++o) {
                const unsigned long long a = acc[t][o];
                cur[t * 8 + o] = __uint_as_float((unsigned)a) +
                                 __uint_as_float((unsigned)(a >> 32));
            }
#pragma unroll
        for (int off = 16; off >= 1; off >>= 1) {
#pragma unroll
            for (int j = 0; j < off; ++j)
                cur[j] += __shfl_xor_sync(0xffffffffu, cur[j + off], off);
        }
        // lane l: cur[0] = this warp's total of value l

        float* redk = red + (k & 1) * 256;
        redk[wid * 32 + lane] = cur[0];
        bar_cons();                    // red visible; all consumer buf reads done
        if (tid == 0) mbar_arrive(emptyb(slot));   // single release arrive

        if (wid == 0) {
            float s = bval;
#pragma unroll
            for (int w8 = 0; w8 < 8; ++w8) s += redk[w8 * 32 + lane];
            out[(size_t)(s0 + k * gridn) * 32 + lane] = s;
        }

        if (++slot == NBUF) { slot = 0; phase ^= 1; }
    }
}

extern "C" void kernel_launch(void* const* d_in, const int* in_sizes, int n_in,
                              void* d_out, int out_size) {
    const int*   ids  = (const int*)  d_in[0];
    const float* M    = (const float*)d_in[1];
    const float* W    = (const float*)d_in[2];
    const float* bias = (const float*)d_in[3];
    float*       out  = (float*)d_out;

    cudaFuncSetAttribute(gather_proj_r14,
                         cudaFuncAttributeMaxDynamicSharedMemorySize, SM_TOT);

    int nsm = 148;
    cudaDeviceGetAttribute(&nsm, cudaDevAttrMultiProcessorCount, 0);

    gather_proj_r14<<<nsm, NTHR, SM_TOT>>>(ids, M, W, bias, out);
}

// round 16
// speedup vs baseline: 1.0077x; 1.0077x over previous
#include <cuda_runtime.h>
#include <cstdint>

// ItemEncoder R16: R12 (best, 20.96us) + L2 PREFETCH of gathered rows.
//   out[t,:] = M[ids[t],:] @ W^T + b ; 12800 tokens, D=2000, O=8.
//
// Why: all transports plateau at ~14-21 B/cyc/SM = per-SM outstanding-miss
// window (~8 KB) / DRAM latency. cp.async.bulk.prefetch.L2.global is
// fire-and-forget (no SM-side tracker, no data return): producer prefetches
// stage k+PF to L2; the real bulk copy then completes at L2 latency
// (~250 cyc vs ~570) -> per-SM BW ~2x through the same window.
//
// Everything else is R12 verbatim: 6-slot bulk ring, 8 consumer warps with
// XOR-rotated W in registers, selection-free butterfly, single-arrive
// empty release.

static constexpr int NTOK  = 12800;
static constexpr int D     = 2000;
static constexpr int ROWB  = D * 4;          // 8000 B
static constexpr int QPR   = D / 4;          // 500
static constexpr int STOK  = 4;
static constexpr int NSTG  = NTOK / STOK;    // 3200
static constexpr int NTHR  = 288;
static constexpr int NCONS = 256;
static constexpr int NBUF  = 6;
static constexpr int PF    = 10;             // prefetch lookahead (stages)
static constexpr int STAGEB  = STOK * ROWB;  // 32000
static constexpr int BSTRIDE = 32256;        // +256 B zeroed pad (quads 500..511)
static constexpr int SM_RED  = NBUF * BSTRIDE;       // 193536; red 2 x 1024 B
static constexpr int SM_MBAR = SM_RED + 2048;
static constexpr int SM_TOT  = SM_MBAR + NBUF * 16;

__device__ __forceinline__ void ffma2(unsigned long long &acc,
                                      unsigned long long a,
                                      unsigned long long b) {
    asm("fma.rn.f32x2 %0, %1, %2, %0;" : "+l"(acc) : "l"(a), "l"(b));
}
__device__ __forceinline__ void mbar_init(uint32_t a, uint32_t cnt) {
    asm volatile("mbarrier.init.shared.b64 [%0], %1;" :: "r"(a), "r"(cnt) : "memory");
}
__device__ __forceinline__ void mbar_expect_tx(uint32_t a, uint32_t bytes) {
    asm volatile("mbarrier.arrive.expect_tx.shared.b64 _, [%0], %1;"
                 :: "r"(a), "r"(bytes) : "memory");
}
__device__ __forceinline__ void mbar_arrive(uint32_t a) {
    asm volatile("mbarrier.arrive.shared.b64 _, [%0];" :: "r"(a) : "memory");
}
__device__ __forceinline__ void mbar_wait(uint32_t a, uint32_t parity) {
    asm volatile(
        "{\n\t.reg .pred P;\n\t"
        "WL_%=:\n\t"
        "mbarrier.try_wait.parity.acquire.cta.shared::cta.b64 P, [%0], %1, 0x989680;\n\t"
        "@P bra WD_%=;\n\t"
        "bra WL_%=;\n\t"
        "WD_%=:\n\t}"
        :: "r"(a), "r"(parity) : "memory");
}
__device__ __forceinline__ void bulk_cp(uint32_t smem_dst, const void* gmem_src,
                                        uint32_t bytes, uint32_t mbar) {
    asm volatile(
        "cp.async.bulk.shared::cta.global.mbarrier::complete_tx::bytes "
        "[%0], [%1], %2, [%3];"
        :: "r"(smem_dst), "l"(gmem_src), "r"(bytes), "r"(mbar) : "memory");
}
__device__ __forceinline__ void l2_prefetch(const void* gmem_src, uint32_t bytes) {
    asm volatile("cp.async.bulk.prefetch.L2.global [%0], %1;"
                 :: "l"(gmem_src), "r"(bytes) : "memory");
}
__device__ __forceinline__ void bar_cons() {     // consumers only (256 threads)
    asm volatile("bar.sync 1, %0;" :: "n"(NCONS) : "memory");
}

__global__ void __launch_bounds__(NTHR, 1)
gather_proj_r16(const int*   __restrict__ ids,
                const float* __restrict__ M,
                const float* __restrict__ W,
                const float* __restrict__ bias,
                float*       __restrict__ out)
{
    extern __shared__ char smem[];
    const uint32_t smem_u32 = (uint32_t)__cvta_generic_to_shared(smem);
    const int tid  = threadIdx.x;
    const int lane = tid & 31;
    const int wid  = tid >> 5;
    const int lt   = lane >> 3;   // token rotation (2 bits)
    const int lo   = lane & 7;    // output rotation (3 bits)

    const int gridn  = gridDim.x;
    const int s0     = blockIdx.x;
    const int nLocal = (NSTG - s0 + gridn - 1) / gridn;

    auto fullb  = [&](int s) -> uint32_t { return smem_u32 + SM_MBAR + s * 16; };
    auto emptyb = [&](int s) -> uint32_t { return smem_u32 + SM_MBAR + s * 16 + 8; };

    // ---- init: mbarriers + zero ring pads ----
    if (tid == 0) {
#pragma unroll
        for (int s = 0; s < NBUF; ++s) {
            mbar_init(fullb(s), 1);    // armed by producer expect_tx
            mbar_init(emptyb(s), 1);   // single arrive by tid0 after group bar
        }
    }
    if (tid < NBUF * 16) {             // zero 6 x 256 B pads (quads 500..511)
        int b = tid >> 4, qq = tid & 15;
        *(float4*)(smem + b * BSTRIDE + STAGEB + qq * 16) =
            make_float4(0.f, 0.f, 0.f, 0.f);
    }
    __syncthreads();                   // mbarriers + pads visible to all

    if (wid == 8) {
        // ================= producer (lane 0) =================
        if (lane == 0) {
            const char* Mb = (const char*)M;
            // prologue: L2-prefetch stages 0..PF-1
            for (int j = 0; j < PF && j < nLocal; ++j) {
                const int4 pi = __ldg((const int4*)ids + (s0 + j * gridn));
                l2_prefetch(Mb + (size_t)pi.x * ROWB, ROWB);
                l2_prefetch(Mb + (size_t)pi.y * ROWB, ROWB);
                l2_prefetch(Mb + (size_t)pi.z * ROWB, ROWB);
                l2_prefetch(Mb + (size_t)pi.w * ROWB, ROWB);
            }
            int phase = 1;             // fresh empty barriers: first waits pass
            int4 nid = __ldg((const int4*)ids + s0);   // stage 0 ids
            for (int k = 0; k < nLocal; ++k) {
                const int slot = k % NBUF;
                // L2-prefetch stage k+PF (fire-and-forget, no SM tracker)
                if (k + PF < nLocal) {
                    const int4 pi = __ldg((const int4*)ids + (s0 + (k + PF) * gridn));
                    l2_prefetch(Mb + (size_t)pi.x * ROWB, ROWB);
                    l2_prefetch(Mb + (size_t)pi.y * ROWB, ROWB);
                    l2_prefetch(Mb + (size_t)pi.z * ROWB, ROWB);
                    l2_prefetch(Mb + (size_t)pi.w * ROWB, ROWB);
                }
                mbar_wait(emptyb(slot), phase);
                const uint32_t dst = smem_u32 + slot * BSTRIDE;
                mbar_expect_tx(fullb(slot), STAGEB);
                bulk_cp(dst,            Mb + (size_t)nid.x * ROWB, ROWB, fullb(slot));
                bulk_cp(dst + ROWB,     Mb + (size_t)nid.y * ROWB, ROWB, fullb(slot));
                bulk_cp(dst + 2 * ROWB, Mb + (size_t)nid.z * ROWB, ROWB, fullb(slot));
                bulk_cp(dst + 3 * ROWB, Mb + (size_t)nid.w * ROWB, ROWB, fullb(slot));
                if (k + 1 < nLocal)    // ids pipelined one stage ahead
                    nid = __ldg((const int4*)ids + (s0 + (k + 1) * gridn));
                if (slot == NBUF - 1) phase ^= 1;
            }
        }
        return;
    }

    // ================= consumers (warps 0-7) =================
    const float bval = __ldg(bias + (lane & 7));

    // W into registers, XOR-rotated by lo: reg slot o holds W row (o^lo).
    // Uncoalesced, but executed exactly once. Zeroed for OOB quads.
    ulonglong2 w[2][8];
#pragma unroll
    for (int it = 0; it < 2; ++it) {
        const int q = wid * 64 + it * 32 + lane;
#pragma unroll
        for (int o = 0; o < 8; ++o) {
            if (q < QPR) w[it][o] = __ldg((const ulonglong2*)W + (o ^ lo) * QPR + q);
            else         w[it][o] = make_ulonglong2(0ull, 0ull);
        }
    }

    float* red = (float*)(smem + SM_RED);
    int slot = 0, phase = 0;

    for (int k = 0; k < nLocal; ++k) {
        mbar_wait(fullb(slot), phase);
        const char* buf = smem + slot * BSTRIDE;

        unsigned long long acc[4][8];
#pragma unroll
        for (int t = 0; t < 4; ++t)
#pragma unroll
            for (int o = 0; o < 8; ++o) acc[t][o] = 0ull;

#pragma unroll
        for (int it = 0; it < 2; ++it) {
            const int q = wid * 64 + it * 32 + lane;   // 500..511 hit pad, w=0
            // token rows XOR-rotated by lt: v slot t holds token (t^lt)
            ulonglong2 v[4];
#pragma unroll
            for (int t = 0; t < 4; ++t)
                v[t] = *(const ulonglong2*)(buf + (t ^ lt) * ROWB + q * 16);
#pragma unroll
            for (int t = 0; t < 4; ++t)
#pragma unroll
                for (int o = 0; o < 8; ++o) {
                    ffma2(acc[t][o], v[t].x, w[it][o].x);
                    ffma2(acc[t][o], v[t].y, w[it][o].y);
                }
        }
        // acc slot j = t*8+o holds partial of value (t^lt)*8+(o^lo) = j^lane

        // ---- collapse f32x2 halves -> 32 scalars ----
        float cur[32];
#pragma unroll
        for (int t = 0; t < 4; ++t)
#pragma unroll
            for (int o = 0; o < 8; ++o) {
                const unsigned long long a = acc[t][o];
                cur[t * 8 + o] = __uint_as_float((unsigned)a) +
                                 __uint_as_float((unsigned)(a >> 32));
            }

        // ---- selection-free butterfly: 31 shfl + 31 add ----
#pragma unroll
        for (int off = 16; off >= 1; off >>= 1) {
#pragma unroll
            for (int j = 0; j < off; ++j)
                cur[j] += __shfl_xor_sync(0xffffffffu, cur[j + off], off);
        }
        // lane l: cur[0] = this warp's total of value l (token l>>3, out l&7)

        float* redk = red + (k & 1) * 256;
        redk[wid * 32 + lane] = cur[0];
        bar_cons();                    // red visible; ALL consumer buf reads done
        if (tid == 0) mbar_arrive(emptyb(slot));   // single release arrive

        if (wid == 0) {
            float s = bval;
#pragma unroll
            for (int w8 = 0; w8 < 8; ++w8) s += redk[w8 * 32 + lane];
            out[(size_t)(s0 + k * gridn) * 32 + lane] = s;
        }

        if (++slot == NBUF) { slot = 0; phase ^= 1; }
    }
}

extern "C" void kernel_launch(void* const* d_in, const int* in_sizes, int n_in,
                              void* d_out, int out_size) {
    const int*   ids  = (const int*)  d_in[0];
    const float* M    = (const float*)d_in[1];
    const float* W    = (const float*)d_in[2];
    const float* bias = (const float*)d_in[3];
    float*       out  = (float*)d_out;

    cudaFuncSetAttribute(gather_proj_r16,
                         cudaFuncAttributeMaxDynamicSharedMemorySize, SM_TOT);

    int nsm = 148;
    cudaDeviceGetAttribute(&nsm, cudaDevAttrMultiProcessorCount, 0);

    gather_proj_r16<<<nsm, NTHR, SM_TOT>>>(ids, M, W, bias, out);
}

// round 17
// speedup vs baseline: 1.4556x; 1.4444x over previous
#include <cuda_runtime.h>
#include <cstdint>

// ItemEncoder R17: R12 (best, 20.96us) with ONE FULL-MBARRIER PER ROW COPY.
//   out[t,:] = M[ids[t],:] @ W^T + b ; 12800 tokens, D=2000, O=8.
//
// Hypothesis: the invariant ~16 B/cyc/SM bulk wall is the per-stage
// mbarrier's complete_tx counter being updated serially per line
// (~252 lines x ~8 cyc = ~2000 cyc = observed cadence). Splitting the
// 4 row copies across 4 mbarriers quadruples completion bandwidth.
// Everything else is R12 verbatim: 6-slot ring, 8 consumer warps,
// XOR-rotated W in registers, selection-free butterfly, single-arrive
// empty release.

static constexpr int NTOK  = 12800;
static constexpr int D     = 2000;
static constexpr int ROWB  = D * 4;          // 8000 B
static constexpr int QPR   = D / 4;          // 500
static constexpr int STOK  = 4;
static constexpr int NSTG  = NTOK / STOK;    // 3200
static constexpr int NTHR  = 288;
static constexpr int NCONS = 256;
static constexpr int NBUF  = 6;
static constexpr int STAGEB  = STOK * ROWB;  // 32000
static constexpr int BSTRIDE = 32256;        // +256 B zeroed pad (quads 500..511)
static constexpr int SM_RED  = NBUF * BSTRIDE;       // 193536; red 2 x 1024 B
static constexpr int SM_MBAR = SM_RED + 2048;
// 24 full mbars (4 per slot) + 6 empty mbars, 8 B each
static constexpr int SM_TOT  = SM_MBAR + (NBUF * 4 + NBUF) * 8;

__device__ __forceinline__ void ffma2(unsigned long long &acc,
                                      unsigned long long a,
                                      unsigned long long b) {
    asm("fma.rn.f32x2 %0, %1, %2, %0;" : "+l"(acc) : "l"(a), "l"(b));
}
__device__ __forceinline__ void mbar_init(uint32_t a, uint32_t cnt) {
    asm volatile("mbarrier.init.shared.b64 [%0], %1;" :: "r"(a), "r"(cnt) : "memory");
}
__device__ __forceinline__ void mbar_expect_tx(uint32_t a, uint32_t bytes) {
    asm volatile("mbarrier.arrive.expect_tx.shared.b64 _, [%0], %1;"
                 :: "r"(a), "r"(bytes) : "memory");
}
__device__ __forceinline__ void mbar_arrive(uint32_t a) {
    asm volatile("mbarrier.arrive.shared.b64 _, [%0];" :: "r"(a) : "memory");
}
__device__ __forceinline__ void mbar_wait(uint32_t a, uint32_t parity) {
    asm volatile(
        "{\n\t.reg .pred P;\n\t"
        "WL_%=:\n\t"
        "mbarrier.try_wait.parity.acquire.cta.shared::cta.b64 P, [%0], %1, 0x989680;\n\t"
        "@P bra WD_%=;\n\t"
        "bra WL_%=;\n\t"
        "WD_%=:\n\t}"
        :: "r"(a), "r"(parity) : "memory");
}
__device__ __forceinline__ void bulk_cp(uint32_t smem_dst, const void* gmem_src,
                                        uint32_t bytes, uint32_t mbar) {
    asm volatile(
        "cp.async.bulk.shared::cta.global.mbarrier::complete_tx::bytes "
        "[%0], [%1], %2, [%3];"
        :: "r"(smem_dst), "l"(gmem_src), "r"(bytes), "r"(mbar) : "memory");
}
__device__ __forceinline__ void bar_cons() {     // consumers only (256 threads)
    asm volatile("bar.sync 1, %0;" :: "n"(NCONS) : "memory");
}

__global__ void __launch_bounds__(NTHR, 1)
gather_proj_r17(const int*   __restrict__ ids,
                const float* __restrict__ M,
                const float* __restrict__ W,
                const float* __restrict__ bias,
                float*       __restrict__ out)
{
    extern __shared__ char smem[];
    const uint32_t smem_u32 = (uint32_t)__cvta_generic_to_shared(smem);
    const int tid  = threadIdx.x;
    const int lane = tid & 31;
    const int wid  = tid >> 5;
    const int lt   = lane >> 3;   // token rotation (2 bits)
    const int lo   = lane & 7;    // output rotation (3 bits)

    const int gridn  = gridDim.x;
    const int s0     = blockIdx.x;
    const int nLocal = (NSTG - s0 + gridn - 1) / gridn;

    // 4 full mbars per slot (one per row copy) + 1 empty mbar per slot
    auto fullb  = [&](int s, int r) -> uint32_t {
        return smem_u32 + SM_MBAR + (s * 4 + r) * 8;
    };
    auto emptyb = [&](int s) -> uint32_t {
        return smem_u32 + SM_MBAR + NBUF * 4 * 8 + s * 8;
    };

    // ---- init: mbarriers + zero ring pads ----
    if (tid == 0) {
#pragma unroll
        for (int s = 0; s < NBUF; ++s) {
#pragma unroll
            for (int r = 0; r < 4; ++r) mbar_init(fullb(s, r), 1);
            mbar_init(emptyb(s), 1);   // single arrive by tid0 after group bar
        }
    }
    if (tid < NBUF * 16) {             // zero 6 x 256 B pads (quads 500..511)
        int b = tid >> 4, qq = tid & 15;
        *(float4*)(smem + b * BSTRIDE + STAGEB + qq * 16) =
            make_float4(0.f, 0.f, 0.f, 0.f);
    }
    __syncthreads();                   // mbarriers + pads visible to all

    if (wid == 8) {
        // ================= producer (lane 0) =================
        if (lane == 0) {
            const char* Mb = (const char*)M;
            int phase = 1;             // fresh empty barriers: first waits pass
            int4 nid = __ldg((const int4*)ids + s0);   // stage 0 ids
            for (int k = 0; k < nLocal; ++k) {
                const int slot = k % NBUF;
                mbar_wait(emptyb(slot), phase);
                const uint32_t dst = smem_u32 + slot * BSTRIDE;
                // one mbarrier per row copy -> parallel completion counters
                mbar_expect_tx(fullb(slot, 0), ROWB);
                bulk_cp(dst,            Mb + (size_t)nid.x * ROWB, ROWB, fullb(slot, 0));
                mbar_expect_tx(fullb(slot, 1), ROWB);
                bulk_cp(dst + ROWB,     Mb + (size_t)nid.y * ROWB, ROWB, fullb(slot, 1));
                mbar_expect_tx(fullb(slot, 2), ROWB);
                bulk_cp(dst + 2 * ROWB, Mb + (size_t)nid.z * ROWB, ROWB, fullb(slot, 2));
                mbar_expect_tx(fullb(slot, 3), ROWB);
                bulk_cp(dst + 3 * ROWB, Mb + (size_t)nid.w * ROWB, ROWB, fullb(slot, 3));
                if (k + 1 < nLocal)    // ids pipelined one stage ahead
                    nid = __ldg((const int4*)ids + (s0 + (k + 1) * gridn));
                if (slot == NBUF - 1) phase ^= 1;
            }
        }
        return;
    }

    // ================= consumers (warps 0-7) =================
    const float bval = __ldg(bias + (lane & 7));

    // W into registers, XOR-rotated by lo: reg slot o holds W row (o^lo).
    // Uncoalesced, but executed exactly once. Zeroed for OOB quads.
    ulonglong2 w[2][8];
#pragma unroll
    for (int it = 0; it < 2; ++it) {
        const int q = wid * 64 + it * 32 + lane;
#pragma unroll
        for (int o = 0; o < 8; ++o) {
            if (q < QPR) w[it][o] = __ldg((const ulonglong2*)W + (o ^ lo) * QPR + q);
            else         w[it][o] = make_ulonglong2(0ull, 0ull);
        }
    }

    float* red = (float*)(smem + SM_RED);
    int slot = 0, phase = 0;

    for (int k = 0; k < nLocal; ++k) {
        // wait all 4 row copies of this stage (independent counters)
        mbar_wait(fullb(slot, 0), phase);
        mbar_wait(fullb(slot, 1), phase);
        mbar_wait(fullb(slot, 2), phase);
        mbar_wait(fullb(slot, 3), phase);
        const char* buf = smem + slot * BSTRIDE;

        unsigned long long acc[4][8];
#pragma unroll
        for (int t = 0; t < 4; ++t)
#pragma unroll
            for (int o = 0; o < 8; ++o) acc[t][o] = 0ull;

#pragma unroll
        for (int it = 0; it < 2; ++it) {
            const int q = wid * 64 + it * 32 + lane;   // 500..511 hit pad, w=0
            // token rows XOR-rotated by lt: v slot t holds token (t^lt)
            ulonglong2 v[4];
#pragma unroll
            for (int t = 0; t < 4; ++t)
                v[t] = *(const ulonglong2*)(buf + (t ^ lt) * ROWB + q * 16);
#pragma unroll
            for (int t = 0; t < 4; ++t)
#pragma unroll
                for (int o = 0; o < 8; ++o) {
                    ffma2(acc[t][o], v[t].x, w[it][o].x);
                    ffma2(acc[t][o], v[t].y, w[it][o].y);
                }
        }
        // acc slot j = t*8+o holds partial of value (t^lt)*8+(o^lo) = j^lane

        // ---- collapse f32x2 halves -> 32 scalars ----
        float cur[32];
#pragma unroll
        for (int t = 0; t < 4; ++t)
#pragma unroll
            for (int o = 0; o < 8; ++o) {
                const unsigned long long a = acc[t][o];
                cur[t * 8 + o] = __uint_as_float((unsigned)a) +
                                 __uint_as_float((unsigned)(a >> 32));
            }

        // ---- selection-free butterfly: 31 shfl + 31 add ----
#pragma unroll
        for (int off = 16; off >= 1; off >>= 1) {
#pragma unroll
            for (int j = 0; j < off; ++j)
                cur[j] += __shfl_xor_sync(0xffffffffu, cur[j + off], off);
        }
        // lane l: cur[0] = this warp's total of value l (token l>>3, out l&7)

        float* redk = red + (k & 1) * 256;
        redk[wid * 32 + lane] = cur[0];
        bar_cons();                    // red visible; ALL consumer buf reads done
        if (tid == 0) mbar_arrive(emptyb(slot));   // single release arrive

        if (wid == 0) {
            float s = bval;
#pragma unroll
            for (int w8 = 0; w8 < 8; ++w8) s += redk[w8 * 32 + lane];
            out[(size_t)(s0 + k * gridn) * 32 + lane] = s;
        }

        if (++slot == NBUF) { slot = 0; phase ^= 1; }
    }
}

extern "C" void kernel_launch(void* const* d_in, const int* in_sizes, int n_in,
                              void* d_out, int out_size) {
    const int*   ids  = (const int*)  d_in[0];
    const float* M    = (const float*)d_in[1];
    const float* W    = (const float*)d_in[2];
    const float* bias = (const float*)d_in[3];
    float*       out  = (float*)d_out;

    cudaFuncSetAttribute(gather_proj_r17,
                         cudaFuncAttributeMaxDynamicSharedMemorySize, SM_TOT);

    int nsm = 148;
    cudaDeviceGetAttribute(&nsm, cudaDevAttrMultiProcessorCount, 0);

    gather_proj_r17<<<nsm, NTHR, SM_TOT>>>(ids, M, W, bias, out);
}